// round 9
// baseline (speedup 1.0000x reference)
#include <cuda_runtime.h>

// APMLSparse: x[B,N,3], y[B,M,3] fp32 -> scalar loss. B=4, N=M=4096.
// Per row: d_j = sqrt(max(||x-y_j||^2,1e-12)), e_j=exp(-d_j), Z=sum e_j.
// Kept = d-ascending prefix while exclusive cumulative mass < 0.8*Z (incl.
// crossing entry, p>1e-10 filter). loss += sum_kept e_j*d_j / Z.
//
// R7 (from R4, the 404us best): TWO full-data passes instead of three.
//  pass 1: dist -> d (regs), exp-mass into 16-bin private banked histogram
//          (hist[bin*512+tid], conflict-free, zero atomics).
//  scan 1: crossing bin c1, mass below it, Z, T.
//  pass 2: below-bin kept mass via ONE predicated FMA (float compare d<c1,
//          no F2I); crossing-bin elements ballot-appended to a smem list.
//  All refinement on the list only (~1-2K elems): one 16-sub-bin histogram
//  round -> final ~140-elem band -> exact O(k^2) rank resolution.
//  Read-and-clear bin reduces (no standalone zeroing); per-thread rcpZ row
//  fold; one block reduce per CTA.

#define NTH  512
#define NPT  8              // 4096 / NTH
#define RPC  8
#define MPTS 4096
#define NB   16
#define CAP  4096           // crossing bin can never overflow this
#define CAP2 512
#define HIST_BYTES (NB * NTH * 4)   // 32 KB

__global__ void apml_zero_out(float* o) { o[0] = 0.0f; }

__global__ __launch_bounds__(NTH, 2)
void apml_kernel(const float* __restrict__ x, const float* __restrict__ y,
                 float* __restrict__ out)
{
    extern __shared__ float hist[];     // NB*NTH floats (32 KB dynamic)
    __shared__ float2 list[CAP];        // 32 KB crossing-bin elements
    __shared__ float  l2d[CAP2];        // final band
    __shared__ float  l2e[CAP2];
    __shared__ float  binTot[NB];
    __shared__ float  warpRed[16];
    __shared__ float  s_ctl[8];  // 0:Z 1:T 2:c1lo 3:c1hi 4:mLo1 5:rcpZ 6:c1(bits)
    __shared__ float  s_ctl2[4]; // 0:lA 1:hA 2:mLo2
    __shared__ int    s_cnt, s_cnt2;

    const int tid = threadIdx.x, lane = tid & 31, wid = tid >> 5;
    const int cpb = MPTS / RPC;                    // 512
    const int b = blockIdx.x / cpb;
    const int rowBase = (blockIdx.x % cpb) * RPC;

    // 8 y-points per thread in registers, reused across RPC rows.
    float yx[NPT], yy[NPT], yz[NPT];
    const float* yb = y + (size_t)b * MPTS * 3;
#pragma unroll
    for (int k = 0; k < NPT; k++) {
        int j = k * NTH + tid;
        yx[k] = yb[j * 3 + 0];
        yy[k] = yb[j * 3 + 1];
        yz[k] = yb[j * 3 + 2];
    }

    // Initial histogram zero (read-and-clear reduces keep it clean after).
    float4* h4 = (float4*)hist;
#pragma unroll
    for (int i = 0; i < NB * NTH / 4 / NTH; i++)
        h4[tid + i * NTH] = make_float4(0.f, 0.f, 0.f, 0.f);

    float ctaAcc = 0.0f;
    __syncthreads();

    for (int r = 0; r < RPC; r++) {
        const float* xp = x + ((size_t)b * MPTS + rowBase + r) * 3;
        const float x0 = __ldg(xp + 0);
        const float x1 = __ldg(xp + 1);
        const float x2 = __ldg(xp + 2);

        // ---- pass 1: distances -> regs, exp-mass -> stage-1 bins (width 1) ----
        float dreg[NPT];
#pragma unroll
        for (int k = 0; k < NPT; k++) {
            float dx = x0 - yx[k];
            float dy = x1 - yy[k];
            float dz = x2 - yz[k];
            float sq = fmaf(dx, dx, fmaf(dy, dy, dz * dz));
            sq = fmaxf(sq, 1e-12f);
            float d = sq * rsqrtf(sq);               // sqrt via MUFU.RSQ + FMUL
            dreg[k] = d;
            float ex = __expf(-d);
            int bin = (int)d;
            bin = bin < (NB - 1) ? bin : (NB - 1);
            hist[bin * NTH + tid] += ex;             // conflict-free column
        }
        __syncthreads();

        // ---- reduce stage-1 bins and zero them: warp w -> bin w ----
        {
            float4* col = (float4*)(hist + wid * NTH);
            float s = 0.f;
#pragma unroll
            for (int i = 0; i < NTH / 4 / 32; i++) {
                float4 v = col[lane + 32 * i];
                s += (v.x + v.y) + (v.z + v.w);
                col[lane + 32 * i] = make_float4(0.f, 0.f, 0.f, 0.f);
            }
#pragma unroll
            for (int o = 16; o; o >>= 1) s += __shfl_xor_sync(0xffffffffu, s, o);
            if (lane == 0) binTot[wid] = s;
        }
        __syncthreads();

        // ---- scan stage 1 (warp 0; 16 live lanes) ----
        if (wid == 0) {
            float mm = (lane < NB) ? binTot[lane] : 0.f;
            float incl = mm;
#pragma unroll
            for (int o = 1; o < 32; o <<= 1) {
                float t = __shfl_up_sync(0xffffffffu, incl, o);
                if (lane >= o) incl += t;
            }
            float total = __shfl_sync(0xffffffffu, incl, 31);
            float T = 0.8f * total;
            float excl = incl - mm;
            unsigned bal = __ballot_sync(0xffffffffu,
                                         (lane < NB) && (excl < T) && (incl >= T));
            int c1 = bal ? (__ffs(bal) - 1) : (NB - 1);
            float mlo = __shfl_sync(0xffffffffu, excl, c1);
            if (lane == 0) {
                s_ctl[0] = total;
                s_ctl[1] = T;
                s_ctl[2] = (float)c1;                              // low edge
                s_ctl[3] = (c1 >= NB - 1) ? 1e30f : (float)(c1 + 1); // high edge
                s_ctl[4] = mlo;
                s_ctl[5] = __frcp_rn(total);
                s_ctl[6] = __int_as_float(c1);
                s_cnt = 0;      // safe: two barriers since prior row's last use
                s_cnt2 = 0;
            }
        }
        __syncthreads();
        const float Z    = s_ctl[0];
        const float T    = s_ctl[1];
        const float c1lo = s_ctl[2];
        const float c1hi = s_ctl[3];
        const float mLo1 = s_ctl[4];
        const float rcpZ = s_ctl[5];
        const int   c1i  = __float_as_int(s_ctl[6]);

        // ---- pass 2: below-bin kept FMA + crossing-bin append (float cmps) ----
        float acc = 0.0f;
#pragma unroll
        for (int k = 0; k < NPT; k++) {
            float d = dreg[k];
            bool below = d < c1lo;
            bool band  = (!below) && (d < c1hi);
            if (below) acc = fmaf(__expf(-d), d, acc);
            unsigned mk = __ballot_sync(0xffffffffu, band);
            if (mk) {
                int leader = __ffs(mk) - 1;
                int base = 0;
                if (lane == leader) base = atomicAdd(&s_cnt, __popc(mk));
                base = __shfl_sync(0xffffffffu, base, leader);
                if (band) {
                    int idx = base + __popc(mk & ((1u << lane) - 1u));
                    list[idx] = make_float2(d, __expf(-d));   // idx < CAP always
                }
            }
        }
        __syncthreads();
        const int cnt = s_cnt;          // <= 4096 by construction

        // ---- round A: 16 sub-bins (width 1/16) over the list only ----
        for (int i = tid; i < cnt; i += NTH) {
            float2 v = list[i];
            int sb = (int)(16.0f * v.x) - (c1i << 4);   // exact 2^4 scaling
            sb = sb < (NB - 1) ? sb : (NB - 1);         // clamp (d>=16 tail)
            hist[sb * NTH + tid] += v.y;
        }
        __syncthreads();

        // ---- reduce sub-bins and zero them ----
        {
            float4* col = (float4*)(hist + wid * NTH);
            float s = 0.f;
#pragma unroll
            for (int i = 0; i < NTH / 4 / 32; i++) {
                float4 v = col[lane + 32 * i];
                s += (v.x + v.y) + (v.z + v.w);
                col[lane + 32 * i] = make_float4(0.f, 0.f, 0.f, 0.f);
            }
#pragma unroll
            for (int o = 16; o; o >>= 1) s += __shfl_xor_sync(0xffffffffu, s, o);
            if (lane == 0) binTot[wid] = s;
        }
        __syncthreads();

        // ---- scan sub-bins ----
        if (wid == 0) {
            float mm = (lane < NB) ? binTot[lane] : 0.f;
            float incl = mm;
#pragma unroll
            for (int o = 1; o < 32; o <<= 1) {
                float t = __shfl_up_sync(0xffffffffu, incl, o);
                if (lane >= o) incl += t;
            }
            float excl = incl - mm;
            unsigned bal = __ballot_sync(0xffffffffu,
                (lane < NB) && (mLo1 + excl < T) && (mLo1 + incl >= T));
            int ce = bal ? (__ffs(bal) - 1) : (NB - 1);   // fp-mismatch fallback
            float mlo2 = mLo1 + __shfl_sync(0xffffffffu, excl, ce);
            if (lane == 0) {
                int sb16 = (c1i << 4) + ce;
                s_ctl2[0] = (float)sb16 * 0.0625f;        // exact fp
                s_ctl2[1] = (c1i == NB - 1 && ce == NB - 1)
                              ? 1e30f : (float)(sb16 + 1) * 0.0625f;
                s_ctl2[2] = mlo2;
            }
        }
        __syncthreads();
        const float lA   = s_ctl2[0];
        const float hA   = s_ctl2[1];
        const float mLo2 = s_ctl2[2];

        // ---- pass B over list: kept sub-bins + final band collection ----
        for (int i = tid; i < cnt; i += NTH) {
            float2 v = list[i];
            if (v.x < lA) {
                acc = fmaf(v.y, v.x, acc);
            } else if (v.x < hA) {
                int idx = atomicAdd(&s_cnt2, 1);
                if (idx < CAP2) { l2d[idx] = v.x; l2e[idx] = v.y; }
                else            acc = fmaf(v.y, v.x, acc);   // ~impossible
            }
        }
        __syncthreads();

        // ---- exact O(k^2) rank resolution on the ~140-element band ----
        const int   c2n  = s_cnt2 < CAP2 ? s_cnt2 : CAP2;
        const float Trem = T - mLo2;
        const float eThr = 1e-10f * Z;
        for (int i = tid; i < c2n; i += NTH) {
            float di = l2d[i], ei = l2e[i], rm = 0.f;
            for (int j = 0; j < c2n; j++) {
                float dj = l2d[j];
                rm += ((dj < di) || (dj == di && j < i)) ? l2e[j] : 0.f;
            }
            if (rm < Trem && ei > eThr) acc = fmaf(ei, di, acc);
        }

        // ---- fold row into per-thread accumulator ----
        ctaAcc = fmaf(acc, rcpZ, ctaAcc);
        // ordering: next row's pass-1 + reduce-1 barriers precede the s_cnt
        // reset and any list overwrite, so prior-row reads are safe.
    }

    // ---- one block reduce per CTA ----
#pragma unroll
    for (int o = 16; o; o >>= 1) ctaAcc += __shfl_xor_sync(0xffffffffu, ctaAcc, o);
    if (lane == 0) warpRed[wid] = ctaAcc;
    __syncthreads();
    if (tid == 0) {
        float tot = 0.f;
#pragma unroll
        for (int i = 0; i < 16; i++) tot += warpRed[i];
        atomicAdd(out, tot);
    }
}

extern "C" void kernel_launch(void* const* d_in, const int* in_sizes, int n_in,
                              void* d_out, int out_size)
{
    const float* x = (const float*)d_in[0];
    const float* y = (const float*)d_in[1];
    float* out = (float*)d_out;

    cudaFuncSetAttribute(apml_kernel,
                         cudaFuncAttributeMaxDynamicSharedMemorySize, HIST_BYTES);

    apml_zero_out<<<1, 1>>>(out);
    const int grid = (4 * MPTS) / RPC;   // 2048 CTAs
    apml_kernel<<<grid, NTH, HIST_BYTES>>>(x, y, out);
}